// round 9
// baseline (speedup 1.0000x reference)
#include <cuda_runtime.h>
#include <cuda_fp16.h>

#define M_ROWS 8192
#define N_CLASSES 256
#define DIM 128

// ---------------- scratch (__device__ globals; allocation-free rule) -------
__device__ __align__(16) __half g_hp[N_CLASSES * DIM];
__device__ float g_pnorm[N_CLASSES];

static __device__ __forceinline__ unsigned smem_u32(const void* p) {
    return (unsigned)__cvta_generic_to_shared(p);
}

#define LDM4(d0, d1, d2, d3, a)                                              \
    asm volatile("ldmatrix.sync.aligned.m8n8.x4.shared.b16 {%0,%1,%2,%3}, [%4];" \
                 : "=r"(d0), "=r"(d1), "=r"(d2), "=r"(d3) : "r"(a))

#define MMA16816(c0, c1, c2, c3, a0, a1, a2, a3, b0, b1)                     \
    asm volatile("mma.sync.aligned.m16n8k16.row.col.f32.f16.f16.f32 "        \
                 "{%0,%1,%2,%3}, {%4,%5,%6,%7}, {%8,%9}, {%0,%1,%2,%3};"     \
                 : "+f"(c0), "+f"(c1), "+f"(c2), "+f"(c3)                    \
                 : "r"(a0), "r"(a1), "r"(a2), "r"(a3), "r"(b0), "r"(b1))

#define CP_ASYNC16(dst, src)                                                 \
    asm volatile("cp.async.cg.shared.global [%0], [%1], 16;"                 \
                 :: "r"(dst), "l"(src))

// ---------------------------------------------------------------------------
// k1: prototype builder, one CTA per class. No atomics; int4-vectorized
// label scans, coalesced gather. (unchanged from round 8)
// ---------------------------------------------------------------------------
__global__ void __launch_bounds__(256)
proto_kernel(const float* __restrict__ support,
             const int* __restrict__ labels, int S) {
    __shared__ int   list[4096];
    __shared__ int   wbase[9];
    __shared__ float part[2][DIM];
    __shared__ float red[4];

    int c    = blockIdx.x;
    int tid  = threadIdx.x;
    int lane = tid & 31;
    int wid  = tid >> 5;

    const int4* L4 = (const int4*)labels;
    int n4 = S >> 2;
    int nIter = (n4 + 255) >> 8;

    int cnt = 0;
    #pragma unroll
    for (int i = 0; i < 4; i++) {
        if (i >= nIter) break;
        int idx = tid + i * 256;
        if (idx < n4) {
            int4 v = __ldg(&L4[idx]);
            cnt += (v.x == c) + (v.y == c) + (v.z == c) + (v.w == c);
        }
    }

    int inc = cnt;
    #pragma unroll
    for (int o = 1; o < 32; o <<= 1) {
        int t = __shfl_up_sync(0xffffffffu, inc, o);
        if (lane >= o) inc += t;
    }
    if (lane == 31) wbase[wid + 1] = inc;
    if (tid == 0) wbase[0] = 0;
    __syncthreads();
    if (tid == 0)
        #pragma unroll
        for (int w = 1; w <= 8; w++) wbase[w] += wbase[w - 1];
    __syncthreads();

    int pos = wbase[wid] + inc - cnt;
    #pragma unroll
    for (int i = 0; i < 4; i++) {
        if (i >= nIter) break;
        int idx = tid + i * 256;
        if (idx < n4) {
            int4 v = __ldg(&L4[idx]);
            int r = idx * 4;
            if (v.x == c) list[pos++] = r;
            if (v.y == c) list[pos++] = r + 1;
            if (v.z == c) list[pos++] = r + 2;
            if (v.w == c) list[pos++] = r + 3;
        }
    }
    __syncthreads();

    int total = wbase[8];

    {
        int d    = tid & 127;
        int half = tid >> 7;
        float s = 0.0f;
        int i = half;
        for (; i + 6 < total; i += 8) {
            float a0 = __ldg(&support[(size_t)list[i]     * DIM + d]);
            float a1 = __ldg(&support[(size_t)list[i + 2] * DIM + d]);
            float a2 = __ldg(&support[(size_t)list[i + 4] * DIM + d]);
            float a3 = __ldg(&support[(size_t)list[i + 6] * DIM + d]);
            s += a0; s += a1; s += a2; s += a3;
        }
        for (; i < total; i += 2)
            s += __ldg(&support[(size_t)list[i] * DIM + d]);
        part[half][d] = s;
    }
    __syncthreads();

    if (tid < DIM) {
        float cntf = fmaxf((float)total, 1.0f);
        float v = (part[0][tid] + part[1][tid]) / cntf;
        g_hp[c * DIM + tid] = __float2half_rn(v);

        float q = v * v;
        #pragma unroll
        for (int o = 16; o > 0; o >>= 1)
            q += __shfl_xor_sync(0xffffffffu, q, o);
        if (lane == 0) red[wid] = q;
    }
    __syncthreads();
    if (tid == 0) g_pnorm[c] = red[0] + red[1] + red[2] + red[3];
}

// ---------------------------------------------------------------------------
// k2: fused convert + fp16 tensor-core GEMM.
// out[m][n] = 2*dot(x_m,p_n) - ||x_m||^2 - ||p_n||^2
// BM=BN=64, 256 threads (8 warps), warp grid 2(m)x4(n), warp tile 32x16.
// grid = 128 x 4 = 512 CTAs -> ~28 warps/SM (grid-limited occupancy fix).
// ---------------------------------------------------------------------------
#define BM 64
#define BN 64
#define GEMM_SMEM (BM * DIM * 2 + BN * DIM * 2 + 64 * 17 * 4 + 64 * 4 + 64 * 4)

__global__ void __launch_bounds__(256)
mma_kernel(const float* __restrict__ x, float* __restrict__ out) {
    extern __shared__ __half sm[];
    __half* hA = sm;                          // [64][128]
    __half* hB = sm + BM * DIM;               // [64][128]
    float*  xpart   = (float*)(sm + BM * DIM + BN * DIM);   // [64][17]
    float*  xnorm_s = xpart + 64 * 17;                      // [64]
    float*  pnorm_s = xnorm_s + 64;                         // [64]

    int tid = threadIdx.x;
    int lane = tid & 31;
    int m0 = blockIdx.x * BM;
    int n0 = blockIdx.y * BN;

    // ---- B tile via cp.async (issued first, hides under A loads) ----
    {
        const uint4* ghB = (const uint4*)(g_hp + (size_t)n0 * DIM);
        unsigned sB = smem_u32(hB);
        #pragma unroll
        for (int i = 0; i < 4; i++) {
            int idx = tid + i * 256;
            int row = idx >> 4, c = idx & 15;
            int sw = c ^ (row & 7);
            CP_ASYNC16(sB + (unsigned)(row * 16 + sw) * 16, ghB + idx);
        }
        asm volatile("cp.async.commit_group;");
    }
    if (tid < BN) pnorm_s[tid] = g_pnorm[n0 + tid];

    // ---- load x tile (f32), convert to fp16, swizzled smem; xnorm partials ----
    {
        const float4* gx = (const float4*)(x + (size_t)m0 * DIM);
        uint4* shA = (uint4*)hA;
        #pragma unroll
        for (int i = 0; i < 4; i++) {
            int idx = tid + i * 256;        // 16B fp16 chunk id
            int row = idx >> 4, c = idx & 15;
            float4 v0 = gx[row * 32 + c * 2];
            float4 v1 = gx[row * 32 + c * 2 + 1];

            union { __half2 q[4]; uint4 u; } H;
            H.q[0] = __floats2half2_rn(v0.x, v0.y);
            H.q[1] = __floats2half2_rn(v0.z, v0.w);
            H.q[2] = __floats2half2_rn(v1.x, v1.y);
            H.q[3] = __floats2half2_rn(v1.z, v1.w);

            int sw = c ^ (row & 7);
            shA[row * 16 + sw] = H.u;

            xpart[row * 17 + c] =
                  v0.x * v0.x + v0.y * v0.y + v0.z * v0.z + v0.w * v0.w
                + v1.x * v1.x + v1.y * v1.y + v1.z * v1.z + v1.w * v1.w;
        }
    }
    asm volatile("cp.async.wait_group 0;");
    __syncthreads();

    if (tid < BM) {
        float s = 0.0f;
        #pragma unroll
        for (int c = 0; c < 16; c++) s += xpart[tid * 17 + c];
        xnorm_s[tid] = s;
    }

    int warp = tid >> 5;
    int wm = warp & 1;        // m: 32 rows
    int wn = warp >> 1;       // n: 0..3, 16 cols each
    int grp = lane >> 3, lr = lane & 7;

    int rowA[2], keyA[2];
    #pragma unroll
    for (int ms = 0; ms < 2; ms++) {
        rowA[ms] = wm * 32 + ms * 16 + lr + ((grp & 1) << 3);
        keyA[ms] = rowA[ms] & 7;
    }
    int cAadd = grp >> 1;
    int rowB = wn * 16 + lr + ((grp >> 1) << 3);
    int keyB = rowB & 7;
    int cBadd = grp & 1;

    unsigned baseHA = smem_u32(hA);
    unsigned baseHB = smem_u32(hB);
    unsigned offA[2];
    #pragma unroll
    for (int i = 0; i < 2; i++) offA[i] = rowA[i] * 256;
    unsigned offB = rowB * 256;

    float acc[2][2][4];
    #pragma unroll
    for (int i = 0; i < 2; i++)
        #pragma unroll
        for (int j = 0; j < 2; j++)
            #pragma unroll
            for (int k = 0; k < 4; k++) acc[i][j][k] = 0.0f;

    #pragma unroll
    for (int ks = 0; ks < 8; ks++) {
        int kc = ks * 2;
        unsigned ah[2][4], bh[4];
        #pragma unroll
        for (int ms = 0; ms < 2; ms++) {
            unsigned sw = ((unsigned)((kc + cAadd) ^ keyA[ms])) << 4;
            LDM4(ah[ms][0], ah[ms][1], ah[ms][2], ah[ms][3], baseHA + offA[ms] + sw);
        }
        {
            unsigned sw = ((unsigned)((kc + cBadd) ^ keyB)) << 4;
            LDM4(bh[0], bh[1], bh[2], bh[3], baseHB + offB + sw);
        }
        #pragma unroll
        for (int ms = 0; ms < 2; ms++) {
            #pragma unroll
            for (int ns = 0; ns < 2; ns++) {
                float* c = acc[ms][ns];
                MMA16816(c[0], c[1], c[2], c[3],
                         ah[ms][0], ah[ms][1], ah[ms][2], ah[ms][3],
                         bh[ns * 2], bh[ns * 2 + 1]);
            }
        }
    }
    __syncthreads();   // xnorm_s ready for all threads

    // ---- epilogue: out = 2*dot - xnorm - pnorm ----
    int qrow = lane >> 2;
    int qcol = (lane & 3) * 2;
    #pragma unroll
    for (int ms = 0; ms < 2; ms++) {
        int lrow = wm * 32 + ms * 16 + qrow;
        int mrow = m0 + lrow;
        float xn0 = xnorm_s[lrow];
        float xn1 = xnorm_s[lrow + 8];
        #pragma unroll
        for (int ns = 0; ns < 2; ns++) {
            int nl = wn * 16 + ns * 8 + qcol;
            int n  = n0 + nl;
            float pn0 = pnorm_s[nl];
            float pn1 = pnorm_s[nl + 1];
            float* c = acc[ms][ns];
            float2 o0 = make_float2(2.0f * c[0] - xn0 - pn0,
                                    2.0f * c[1] - xn0 - pn1);
            float2 o1 = make_float2(2.0f * c[2] - xn1 - pn0,
                                    2.0f * c[3] - xn1 - pn1);
            *(float2*)&out[(size_t)mrow * N_CLASSES + n] = o0;
            *(float2*)&out[(size_t)(mrow + 8) * N_CLASSES + n] = o1;
        }
    }
}

// ---------------------------------------------------------------------------
extern "C" void kernel_launch(void* const* d_in, const int* in_sizes, int n_in,
                              void* d_out, int out_size) {
    const float* x       = (const float*)d_in[0];
    const float* support = (const float*)d_in[1];
    const int*   labels  = (const int*)d_in[2];
    float* out = (float*)d_out;

    int S = in_sizes[2];  // 4096

    proto_kernel<<<N_CLASSES, 256>>>(support, labels, S);

    cudaFuncSetAttribute(mma_kernel,
                         cudaFuncAttributeMaxDynamicSharedMemorySize, GEMM_SMEM);
    mma_kernel<<<dim3(M_ROWS / BM, N_CLASSES / BN), 256, GEMM_SMEM>>>(x, out);
}

// round 12
// speedup vs baseline: 1.1604x; 1.1604x over previous
#include <cuda_runtime.h>
#include <cuda_fp16.h>

#define M_ROWS 8192
#define N_CLASSES 256
#define DIM 128

// ---------------- scratch (__device__ globals; allocation-free rule) -------
__device__ __align__(16) __half g_hp[N_CLASSES * DIM];
__device__ float g_pnorm[N_CLASSES];

static __device__ __forceinline__ unsigned smem_u32(const void* p) {
    return (unsigned)__cvta_generic_to_shared(p);
}

#define LDM4(d0, d1, d2, d3, a)                                              \
    asm volatile("ldmatrix.sync.aligned.m8n8.x4.shared.b16 {%0,%1,%2,%3}, [%4];" \
                 : "=r"(d0), "=r"(d1), "=r"(d2), "=r"(d3) : "r"(a))

#define MMA16816(c0, c1, c2, c3, a0, a1, a2, a3, b0, b1)                     \
    asm volatile("mma.sync.aligned.m16n8k16.row.col.f32.f16.f16.f32 "        \
                 "{%0,%1,%2,%3}, {%4,%5,%6,%7}, {%8,%9}, {%0,%1,%2,%3};"     \
                 : "+f"(c0), "+f"(c1), "+f"(c2), "+f"(c3)                    \
                 : "r"(a0), "r"(a1), "r"(a2), "r"(a3), "r"(b0), "r"(b1))

#define CP_ASYNC16(dst, src)                                                 \
    asm volatile("cp.async.cg.shared.global [%0], [%1], 16;"                 \
                 :: "r"(dst), "l"(src))

// ---------------------------------------------------------------------------
// k1: prototype builder, one CTA per class. int4-vectorized label scans,
// coalesced gather. (R8 configuration — part of the 12.77us best run.)
// ---------------------------------------------------------------------------
__global__ void __launch_bounds__(256)
proto_kernel(const float* __restrict__ support,
             const int* __restrict__ labels, int S) {
    __shared__ int   list[4096];
    __shared__ int   wbase[9];
    __shared__ float part[2][DIM];
    __shared__ float red[4];

    int c    = blockIdx.x;
    int tid  = threadIdx.x;
    int lane = tid & 31;
    int wid  = tid >> 5;

    const int4* L4 = (const int4*)labels;
    int n4 = S >> 2;
    int nIter = (n4 + 255) >> 8;

    int cnt = 0;
    #pragma unroll
    for (int i = 0; i < 4; i++) {
        if (i >= nIter) break;
        int idx = tid + i * 256;
        if (idx < n4) {
            int4 v = __ldg(&L4[idx]);
            cnt += (v.x == c) + (v.y == c) + (v.z == c) + (v.w == c);
        }
    }

    int inc = cnt;
    #pragma unroll
    for (int o = 1; o < 32; o <<= 1) {
        int t = __shfl_up_sync(0xffffffffu, inc, o);
        if (lane >= o) inc += t;
    }
    if (lane == 31) wbase[wid + 1] = inc;
    if (tid == 0) wbase[0] = 0;
    __syncthreads();
    if (tid == 0)
        #pragma unroll
        for (int w = 1; w <= 8; w++) wbase[w] += wbase[w - 1];
    __syncthreads();

    int pos = wbase[wid] + inc - cnt;
    #pragma unroll
    for (int i = 0; i < 4; i++) {
        if (i >= nIter) break;
        int idx = tid + i * 256;
        if (idx < n4) {
            int4 v = __ldg(&L4[idx]);
            int r = idx * 4;
            if (v.x == c) list[pos++] = r;
            if (v.y == c) list[pos++] = r + 1;
            if (v.z == c) list[pos++] = r + 2;
            if (v.w == c) list[pos++] = r + 3;
        }
    }
    __syncthreads();

    int total = wbase[8];

    {
        int d    = tid & 127;
        int half = tid >> 7;
        float s = 0.0f;
        int i = half;
        for (; i + 6 < total; i += 8) {
            float a0 = __ldg(&support[(size_t)list[i]     * DIM + d]);
            float a1 = __ldg(&support[(size_t)list[i + 2] * DIM + d]);
            float a2 = __ldg(&support[(size_t)list[i + 4] * DIM + d]);
            float a3 = __ldg(&support[(size_t)list[i + 6] * DIM + d]);
            s += a0; s += a1; s += a2; s += a3;
        }
        for (; i < total; i += 2)
            s += __ldg(&support[(size_t)list[i] * DIM + d]);
        part[half][d] = s;
    }
    __syncthreads();

    if (tid < DIM) {
        float cntf = fmaxf((float)total, 1.0f);
        float v = (part[0][tid] + part[1][tid]) / cntf;
        g_hp[c * DIM + tid] = __float2half_rn(v);

        float q = v * v;
        #pragma unroll
        for (int o = 16; o > 0; o >>= 1)
            q += __shfl_xor_sync(0xffffffffu, q, o);
        if (lane == 0) red[wid] = q;
    }
    __syncthreads();
    if (tid == 0) g_pnorm[c] = red[0] + red[1] + red[2] + red[3];
}

// ---------------------------------------------------------------------------
// k2: fused convert + fp16 tensor-core GEMM (R7 configuration, 8.19us).
// out[m][n] = 2*dot(x_m,p_n) - ||x_m||^2 - ||p_n||^2
// BM=64, BN=128, 256 threads, warp grid 2(m)x4(n), warp tile 32x32.
// grid = 128 x 2 = 256 CTAs, 2 CTAs/SM.
// NOTE: B tile = BN*DIM*2/16 = 2048 uint4 chunks -> 8 iterations x 256 thr.
// ---------------------------------------------------------------------------
#define BM 64
#define BN 128
#define GEMM_SMEM (BM * DIM * 2 + BN * DIM * 2 + 64 * 17 * 4 + 64 * 4 + 128 * 4)

__global__ void __launch_bounds__(256, 2)
mma_kernel(const float* __restrict__ x, float* __restrict__ out) {
    extern __shared__ __half sm[];
    __half* hA = sm;                          // [64][128]
    __half* hB = sm + BM * DIM;               // [128][128]
    float*  xpart   = (float*)(sm + BM * DIM + BN * DIM);   // [64][17]
    float*  xnorm_s = xpart + 64 * 17;                      // [64]
    float*  pnorm_s = xnorm_s + 64;                         // [128]

    int tid = threadIdx.x;
    int lane = tid & 31;
    int m0 = blockIdx.x * BM;
    int n0 = blockIdx.y * BN;

    // ---- B tile via cp.async: 2048 chunks = 8 iters x 256 threads ----
    {
        const uint4* ghB = (const uint4*)(g_hp + (size_t)n0 * DIM);
        unsigned sB = smem_u32(hB);
        #pragma unroll
        for (int i = 0; i < 8; i++) {
            int idx = tid + i * 256;
            int row = idx >> 4, c = idx & 15;
            int sw = c ^ (row & 7);
            CP_ASYNC16(sB + (unsigned)(row * 16 + sw) * 16, ghB + idx);
        }
        asm volatile("cp.async.commit_group;");
    }
    if (tid < BN) pnorm_s[tid] = g_pnorm[n0 + tid];

    // ---- x tile: 1024 chunks = 4 iters x 256 threads; convert + xnorm ----
    {
        const float4* gx = (const float4*)(x + (size_t)m0 * DIM);
        uint4* shA = (uint4*)hA;
        #pragma unroll
        for (int i = 0; i < 4; i++) {
            int idx = tid + i * 256;        // 16B fp16 chunk id
            int row = idx >> 4, c = idx & 15;
            float4 v0 = gx[row * 32 + c * 2];
            float4 v1 = gx[row * 32 + c * 2 + 1];

            union { __half2 q[4]; uint4 u; } H;
            H.q[0] = __floats2half2_rn(v0.x, v0.y);
            H.q[1] = __floats2half2_rn(v0.z, v0.w);
            H.q[2] = __floats2half2_rn(v1.x, v1.y);
            H.q[3] = __floats2half2_rn(v1.z, v1.w);

            int sw = c ^ (row & 7);
            shA[row * 16 + sw] = H.u;

            xpart[row * 17 + c] =
                  v0.x * v0.x + v0.y * v0.y + v0.z * v0.z + v0.w * v0.w
                + v1.x * v1.x + v1.y * v1.y + v1.z * v1.z + v1.w * v1.w;
        }
    }
    asm volatile("cp.async.wait_group 0;");
    __syncthreads();

    // xnorm reduce (64 threads; consumed after the post-MMA sync)
    if (tid < BM) {
        float s = 0.0f;
        #pragma unroll
        for (int c = 0; c < 16; c++) s += xpart[tid * 17 + c];
        xnorm_s[tid] = s;
    }

    int warp = tid >> 5;
    int wm = warp & 1;        // m, 32 rows each
    int wn = warp >> 1;       // n, 32 cols each
    int grp = lane >> 3, lr = lane & 7;

    int rowA[2], keyA[2];
    #pragma unroll
    for (int ms = 0; ms < 2; ms++) {
        rowA[ms] = wm * 32 + ms * 16 + lr + ((grp & 1) << 3);
        keyA[ms] = rowA[ms] & 7;
    }
    int cAadd = grp >> 1;
    int rowB[2], keyB[2];
    #pragma unroll
    for (int np = 0; np < 2; np++) {
        rowB[np] = wn * 32 + np * 16 + lr + ((grp >> 1) << 3);
        keyB[np] = rowB[np] & 7;
    }
    int cBadd = grp & 1;

    unsigned baseHA = smem_u32(hA);
    unsigned baseHB = smem_u32(hB);
    unsigned offA[2], offB[2];
    #pragma unroll
    for (int i = 0; i < 2; i++) { offA[i] = rowA[i] * 256; offB[i] = rowB[i] * 256; }

    float acc[2][4][4];
    #pragma unroll
    for (int i = 0; i < 2; i++)
        #pragma unroll
        for (int j = 0; j < 4; j++)
            #pragma unroll
            for (int k = 0; k < 4; k++) acc[i][j][k] = 0.0f;

    #pragma unroll
    for (int ks = 0; ks < 8; ks++) {
        int kc = ks * 2;
        unsigned ah[2][4], bh[2][4];
        #pragma unroll
        for (int ms = 0; ms < 2; ms++) {
            unsigned sw = ((unsigned)((kc + cAadd) ^ keyA[ms])) << 4;
            LDM4(ah[ms][0], ah[ms][1], ah[ms][2], ah[ms][3], baseHA + offA[ms] + sw);
        }
        #pragma unroll
        for (int np = 0; np < 2; np++) {
            unsigned sw = ((unsigned)((kc + cBadd) ^ keyB[np])) << 4;
            LDM4(bh[np][0], bh[np][1], bh[np][2], bh[np][3], baseHB + offB[np] + sw);
        }
        #pragma unroll
        for (int ms = 0; ms < 2; ms++) {
            #pragma unroll
            for (int ns = 0; ns < 4; ns++) {
                int np = ns >> 1, o = (ns & 1) * 2;
                float* c = acc[ms][ns];
                MMA16816(c[0], c[1], c[2], c[3],
                         ah[ms][0], ah[ms][1], ah[ms][2], ah[ms][3],
                         bh[np][o], bh[np][o + 1]);
            }
        }
    }
    __syncthreads();   // xnorm_s ready for all threads

    // ---- epilogue: out = 2*dot - xnorm - pnorm ----
    int qrow = lane >> 2;
    int qcol = (lane & 3) * 2;
    #pragma unroll
    for (int ms = 0; ms < 2; ms++) {
        int lrow = wm * 32 + ms * 16 + qrow;
        int mrow = m0 + lrow;
        float xn0 = xnorm_s[lrow];
        float xn1 = xnorm_s[lrow + 8];
        #pragma unroll
        for (int ns = 0; ns < 4; ns++) {
            int nl = wn * 32 + ns * 8 + qcol;
            int n  = n0 + nl;
            float pn0 = pnorm_s[nl];
            float pn1 = pnorm_s[nl + 1];
            float* c = acc[ms][ns];
            float2 o0 = make_float2(2.0f * c[0] - xn0 - pn0,
                                    2.0f * c[1] - xn0 - pn1);
            float2 o1 = make_float2(2.0f * c[2] - xn1 - pn0,
                                    2.0f * c[3] - xn1 - pn1);
            *(float2*)&out[(size_t)mrow * N_CLASSES + n] = o0;
            *(float2*)&out[(size_t)(mrow + 8) * N_CLASSES + n] = o1;
        }
    }
}

// ---------------------------------------------------------------------------
extern "C" void kernel_launch(void* const* d_in, const int* in_sizes, int n_in,
                              void* d_out, int out_size) {
    const float* x       = (const float*)d_in[0];
    const float* support = (const float*)d_in[1];
    const int*   labels  = (const int*)d_in[2];
    float* out = (float*)d_out;

    int S = in_sizes[2];  // 4096

    proto_kernel<<<N_CLASSES, 256>>>(support, labels, S);

    cudaFuncSetAttribute(mma_kernel,
                         cudaFuncAttributeMaxDynamicSharedMemorySize, GEMM_SMEM);
    mma_kernel<<<dim3(M_ROWS / BM, N_CLASSES / BN), 256, GEMM_SMEM>>>(x, out);
}